// round 12
// baseline (speedup 1.0000x reference)
#include <cuda_runtime.h>
#include <math.h>
#include <stdint.h>

// ---------------- problem constants ----------------
#define Bb 4
#define Lseq 1024
#define INDIM 46
#define Dm 256
#define DSm 64
#define Kc 4
#define NLAY 4
#define DI 512
#define HDm 64
#define Hh 8
#define XBCd 640
#define DIPd 1160
#define DFFd 512
#define AHn 4
#define AHDd 64
#define ROWS (Bb*Lseq)
#define NCH 16

typedef unsigned long long u64;

// ---------------- device scratch ----------------
__device__ float g_h[ROWS*Dm];
__device__ float g_lnbuf[ROWS*Dm];
__device__ float g_zx[ROWS*DIPd];
__device__ float g_xbc[ROWS*XBCd];
__device__ float g_dt[Bb*Hh*Lseq];
__device__ float g_cA[Bb*Hh*Lseq];
__device__ float g_E[Bb*Hh*NCH];
__device__ float g_G[(size_t)Bb*Hh*NCH*4096];
__device__ float g_Hst[(size_t)Bb*Hh*NCH*4096];
__device__ float g_y[ROWS*DI];
__device__ float g_qkv[ROWS*3*Dm];
__device__ float g_attnO[ROWS*Dm];
__device__ float g_ff2[ROWS*DFFd];
__device__ float g_hm[Bb*Dm];

__device__ __forceinline__ float siluf(float x){ return x / (1.f + expf(-x)); }
__device__ __forceinline__ float geluf(float x){ return 0.5f*x*(1.f + erff(x*0.70710678118654752f)); }

// ---------------- packed fp32x2 helpers ----------------
__device__ __forceinline__ u64 pk2(float x){
    u64 r; asm("mov.b64 %0, {%1, %1};" : "=l"(r) : "f"(x)); return r;
}
__device__ __forceinline__ u64 pk2ab(float a, float b){
    u64 r; asm("mov.b64 %0, {%1, %2};" : "=l"(r) : "f"(a), "f"(b)); return r;
}
__device__ __forceinline__ void fma2(u64 &d, u64 a, u64 b){
    asm("fma.rn.f32x2 %0, %1, %2, %0;" : "+l"(d) : "l"(a), "l"(b));
}
__device__ __forceinline__ float2 upk(u64 v){
    float2 f; asm("mov.b64 {%0, %1}, %2;" : "=f"(f.x), "=f"(f.y) : "l"(v)); return f;
}

// ---------------- embed ----------------
__global__ void embed_kernel(const float* __restrict__ x,
                             const float* __restrict__ in_w,
                             const float* __restrict__ in_b,
                             const float* __restrict__ pos){
    int row = blockIdx.x;
    int d = threadIdx.x;
    __shared__ float xr[INDIM];
    if (d < INDIM) xr[d] = x[(size_t)row*INDIM + d];
    __syncthreads();
    float acc = in_b[d];
#pragma unroll
    for (int i = 0; i < INDIM; i++) acc += xr[i]*in_w[i*Dm + d];
    int l = row & (Lseq-1);
    g_h[(size_t)row*Dm + d] = acc + pos[(size_t)l*Dm + d];
}

// ---------------- layernorm: one warp per row (D=256) ----------------
__global__ __launch_bounds__(256)
void ln_warp(const float* __restrict__ X,
             const float* __restrict__ w,
             const float* __restrict__ b,
             float* __restrict__ out){
    int wr = threadIdx.x >> 5, lane = threadIdx.x & 31;
    int row = blockIdx.x*8 + wr;
    const float* Xr = X + (size_t)row*Dm;
    float4 v0 = *(const float4*)(Xr + lane*8);
    float4 v1 = *(const float4*)(Xr + lane*8 + 4);
    float s = v0.x+v0.y+v0.z+v0.w + v1.x+v1.y+v1.z+v1.w;
#pragma unroll
    for (int off=16; off; off>>=1) s += __shfl_xor_sync(0xffffffffu, s, off);
    float m = s*(1.f/Dm);
    float d0=v0.x-m, d1=v0.y-m, d2=v0.z-m, d3=v0.w-m;
    float d4=v1.x-m, d5=v1.y-m, d6=v1.z-m, d7=v1.w-m;
    float q = d0*d0+d1*d1+d2*d2+d3*d3+d4*d4+d5*d5+d6*d6+d7*d7;
#pragma unroll
    for (int off=16; off; off>>=1) q += __shfl_xor_sync(0xffffffffu, q, off);
    float rs = rsqrtf(q*(1.f/Dm) + 1e-5f);
    float4 w0 = *(const float4*)(w + lane*8);
    float4 w1 = *(const float4*)(w + lane*8 + 4);
    float4 b0 = *(const float4*)(b + lane*8);
    float4 b1 = *(const float4*)(b + lane*8 + 4);
    float4 o0, o1;
    o0.x = d0*rs*w0.x + b0.x; o0.y = d1*rs*w0.y + b0.y;
    o0.z = d2*rs*w0.z + b0.z; o0.w = d3*rs*w0.w + b0.w;
    o1.x = d4*rs*w1.x + b1.x; o1.y = d5*rs*w1.y + b1.y;
    o1.z = d6*rs*w1.z + b1.z; o1.w = d7*rs*w1.w + b1.w;
    *(float4*)(out + (size_t)row*Dm + lane*8)     = o0;
    *(float4*)(out + (size_t)row*Dm + lane*8 + 4) = o1;
}

// ---------------- SGEMM 128x64 tile, 8x4 micro, 256 thr, N-guarded ----------------
__global__ __launch_bounds__(256,2)
void gemm64n(const float* __restrict__ A, const float* __restrict__ W,
             const float* __restrict__ bias, float* __restrict__ C,
             int K, int N, int addC){
    __shared__ float As[2][16][128];
    __shared__ float Bs[2][16][64];
    int tid = threadIdx.x;
    int row0 = blockIdx.y*128, col0 = blockIdx.x*64;
    int ar = tid>>1, ak = (tid&1)*8;
    int bk = tid>>4, bc = (tid&15)*4;
    int ty = tid>>4, tx = tid&15;
    bool bok = (col0 + bc + 4 <= N);
    const float* Ap = A + (size_t)(row0+ar)*K + ak;
    float4 a0,a1,b0;
    a0 = *(const float4*)(Ap);
    a1 = *(const float4*)(Ap+4);
    b0 = make_float4(0.f,0.f,0.f,0.f);
    if (bok) b0 = *(const float4*)(W + (size_t)bk*N + col0+bc);
    int nt = K>>4;
    As[0][ak+0][ar]=a0.x; As[0][ak+1][ar]=a0.y; As[0][ak+2][ar]=a0.z; As[0][ak+3][ar]=a0.w;
    As[0][ak+4][ar]=a1.x; As[0][ak+5][ar]=a1.y; As[0][ak+6][ar]=a1.z; As[0][ak+7][ar]=a1.w;
    *(float4*)&Bs[0][bk][bc] = b0;
    __syncthreads();
    u64 acc2[8][2];
#pragma unroll
    for (int i=0;i<8;i++){ acc2[i][0]=0ULL; acc2[i][1]=0ULL; }
    for (int t=0; t<nt; t++){
        if (t+1 < nt){
            int k0 = (t+1)*16;
            a0 = *(const float4*)(Ap + k0);
            a1 = *(const float4*)(Ap + k0 + 4);
            b0 = make_float4(0.f,0.f,0.f,0.f);
            if (bok) b0 = *(const float4*)(W + (size_t)(k0+bk)*N + col0+bc);
        }
        int buf = t&1;
#pragma unroll
        for (int k=0;k<16;k++){
            float4 av0 = *(const float4*)&As[buf][k][ty*8];
            float4 av1 = *(const float4*)&As[buf][k][ty*8+4];
            ulonglong2 bp = *(const ulonglong2*)&Bs[buf][k][tx*4];
            u64 ap[8];
            ap[0]=pk2(av0.x); ap[1]=pk2(av0.y); ap[2]=pk2(av0.z); ap[3]=pk2(av0.w);
            ap[4]=pk2(av1.x); ap[5]=pk2(av1.y); ap[6]=pk2(av1.z); ap[7]=pk2(av1.w);
#pragma unroll
            for (int i=0;i<8;i++){
                fma2(acc2[i][0], ap[i], bp.x);
                fma2(acc2[i][1], ap[i], bp.y);
            }
        }
        __syncthreads();
        if (t+1 < nt){
            int nb = (t+1)&1;
            As[nb][ak+0][ar]=a0.x; As[nb][ak+1][ar]=a0.y; As[nb][ak+2][ar]=a0.z; As[nb][ak+3][ar]=a0.w;
            As[nb][ak+4][ar]=a1.x; As[nb][ak+5][ar]=a1.y; As[nb][ak+6][ar]=a1.z; As[nb][ak+7][ar]=a1.w;
            *(float4*)&Bs[nb][bk][bc] = b0;
            __syncthreads();
        }
    }
    int cbase = col0 + tx*4;
    if (cbase + 4 <= N){
        float bx=0.f,by=0.f,bz=0.f,bw=0.f;
        if (bias){ bx=bias[cbase]; by=bias[cbase+1]; bz=bias[cbase+2]; bw=bias[cbase+3]; }
#pragma unroll
        for (int i=0;i<8;i++){
            int r = row0 + ty*8 + i;
            size_t idx = (size_t)r*N + cbase;
            float2 p0 = upk(acc2[i][0]);
            float2 p1 = upk(acc2[i][1]);
            float4 v;
            v.x = p0.x+bx; v.y = p0.y+by; v.z = p1.x+bz; v.w = p1.y+bw;
            if (addC){
                float4 o = *(const float4*)&C[idx];
                v.x+=o.x; v.y+=o.y; v.z+=o.z; v.w+=o.w;
            }
            *(float4*)&C[idx] = v;
        }
    }
}

// ---------------- fc1 GEMM, interleaved (x1,x2) pairs, fused gelu-gate ----------------
// CTA: 128 rows x 32 output cols. Smem B position 2c holds x1[col0+c], 2c+1 holds x2[col0+c].
// Thread fragment (4 positions) = 2 complete (x1,x2) output pairs -> fused epilogue, acc2[8][2].
__global__ __launch_bounds__(256,2)
void gemm_fc1(const float* __restrict__ A, const float* __restrict__ W,
              const float* __restrict__ bias, float* __restrict__ C, int K){
    __shared__ float As[2][16][128];
    __shared__ float Bs[2][16][64];
    int tid = threadIdx.x;
    int row0 = blockIdx.y*128, col0 = blockIdx.x*32;
    int ar = tid>>1, ak = (tid&1)*8;
    int bk = tid>>4, bt = tid&15;       // bt covers positions 4bt..4bt+3 = cols col0+2bt, col0+2bt+1
    int ty = tid>>4, tx = tid&15;
    const float* Ap = A + (size_t)(row0+ar)*K + ak;
    float4 a0,a1; float2 b1v,b2v;
    a0 = *(const float4*)(Ap);
    a1 = *(const float4*)(Ap+4);
    b1v = *(const float2*)(W + (size_t)bk*1024 + col0 + 2*bt);
    b2v = *(const float2*)(W + (size_t)bk*1024 + 512 + col0 + 2*bt);
    int nt = K>>4;
    As[0][ak+0][ar]=a0.x; As[0][ak+1][ar]=a0.y; As[0][ak+2][ar]=a0.z; As[0][ak+3][ar]=a0.w;
    As[0][ak+4][ar]=a1.x; As[0][ak+5][ar]=a1.y; As[0][ak+6][ar]=a1.z; As[0][ak+7][ar]=a1.w;
    Bs[0][bk][bt*4+0]=b1v.x; Bs[0][bk][bt*4+1]=b2v.x;
    Bs[0][bk][bt*4+2]=b1v.y; Bs[0][bk][bt*4+3]=b2v.y;
    __syncthreads();
    u64 acc2[8][2];
#pragma unroll
    for (int i=0;i<8;i++){ acc2[i][0]=0ULL; acc2[i][1]=0ULL; }
    for (int t=0; t<nt; t++){
        if (t+1 < nt){
            int k0 = (t+1)*16;
            a0 = *(const float4*)(Ap + k0);
            a1 = *(const float4*)(Ap + k0 + 4);
            b1v = *(const float2*)(W + (size_t)(k0+bk)*1024 + col0 + 2*bt);
            b2v = *(const float2*)(W + (size_t)(k0+bk)*1024 + 512 + col0 + 2*bt);
        }
        int buf = t&1;
#pragma unroll
        for (int k=0;k<16;k++){
            float4 av0 = *(const float4*)&As[buf][k][ty*8];
            float4 av1 = *(const float4*)&As[buf][k][ty*8+4];
            ulonglong2 bp = *(const ulonglong2*)&Bs[buf][k][tx*4];
            u64 ap[8];
            ap[0]=pk2(av0.x); ap[1]=pk2(av0.y); ap[2]=pk2(av0.z); ap[3]=pk2(av0.w);
            ap[4]=pk2(av1.x); ap[5]=pk2(av1.y); ap[6]=pk2(av1.z); ap[7]=pk2(av1.w);
#pragma unroll
            for (int i=0;i<8;i++){
                fma2(acc2[i][0], ap[i], bp.x);
                fma2(acc2[i][1], ap[i], bp.y);
            }
        }
        __syncthreads();
        if (t+1 < nt){
            int nb = (t+1)&1;
            As[nb][ak+0][ar]=a0.x; As[nb][ak+1][ar]=a0.y; As[nb][ak+2][ar]=a0.z; As[nb][ak+3][ar]=a0.w;
            As[nb][ak+4][ar]=a1.x; As[nb][ak+5][ar]=a1.y; As[nb][ak+6][ar]=a1.z; As[nb][ak+7][ar]=a1.w;
            Bs[nb][bk][bt*4+0]=b1v.x; Bs[nb][bk][bt*4+1]=b2v.x;
            Bs[nb][bk][bt*4+2]=b1v.y; Bs[nb][bk][bt*4+3]=b2v.y;
            __syncthreads();
        }
    }
    int c0 = col0 + 2*tx;
    float2 bv1 = *(const float2*)&bias[c0];
    float2 bv2 = *(const float2*)&bias[512 + c0];
#pragma unroll
    for (int i=0;i<8;i++){
        int r = row0 + ty*8 + i;
        float2 p0 = upk(acc2[i][0]);   // (x1[c0], x2[c0])
        float2 p1 = upk(acc2[i][1]);   // (x1[c0+1], x2[c0+1])
        float2 v;
        v.x = geluf(p0.x + bv1.x) * (p0.y + bv2.x);
        v.y = geluf(p1.x + bv1.y) * (p1.y + bv2.y);
        *(float2*)&C[(size_t)r*DFFd + c0] = v;
    }
}

// ---------------- SGEMM 64x64 tile (N=256 GEMMs) ----------------
__global__ __launch_bounds__(128)
void gemm64x64(const float* __restrict__ A, const float* __restrict__ W,
               const float* __restrict__ bias, float* __restrict__ C,
               int K, int N, int addC){
    __shared__ float As[2][16][64];
    __shared__ float Bs[2][16][64];
    int tid = threadIdx.x;
    int row0 = blockIdx.y*64, col0 = blockIdx.x*64;
    int ar = tid>>1, ak = (tid&1)*8;
    int bk = tid>>3, bc = (tid&7)*8;
    int ty = tid>>4, tx = tid&15;
    const float* Ap = A + (size_t)(row0+ar)*K + ak;
    float4 a0,a1,b0,b1;
    a0 = *(const float4*)(Ap);
    a1 = *(const float4*)(Ap+4);
    b0 = *(const float4*)(W + (size_t)bk*N + col0+bc);
    b1 = *(const float4*)(W + (size_t)bk*N + col0+bc+4);
    int nt = K>>4;
    As[0][ak+0][ar]=a0.x; As[0][ak+1][ar]=a0.y; As[0][ak+2][ar]=a0.z; As[0][ak+3][ar]=a0.w;
    As[0][ak+4][ar]=a1.x; As[0][ak+5][ar]=a1.y; As[0][ak+6][ar]=a1.z; As[0][ak+7][ar]=a1.w;
    *(float4*)&Bs[0][bk][bc]   = b0;
    *(float4*)&Bs[0][bk][bc+4] = b1;
    __syncthreads();
    u64 acc2[8][2];
#pragma unroll
    for (int i=0;i<8;i++){ acc2[i][0]=0ULL; acc2[i][1]=0ULL; }
    for (int t=0; t<nt; t++){
        if (t+1 < nt){
            int k0 = (t+1)*16;
            a0 = *(const float4*)(Ap + k0);
            a1 = *(const float4*)(Ap + k0 + 4);
            b0 = *(const float4*)(W + (size_t)(k0+bk)*N + col0+bc);
            b1 = *(const float4*)(W + (size_t)(k0+bk)*N + col0+bc+4);
        }
        int buf = t&1;
#pragma unroll
        for (int k=0;k<16;k++){
            float4 av0 = *(const float4*)&As[buf][k][ty*8];
            float4 av1 = *(const float4*)&As[buf][k][ty*8+4];
            ulonglong2 bp = *(const ulonglong2*)&Bs[buf][k][tx*4];
            u64 ap[8];
            ap[0]=pk2(av0.x); ap[1]=pk2(av0.y); ap[2]=pk2(av0.z); ap[3]=pk2(av0.w);
            ap[4]=pk2(av1.x); ap[5]=pk2(av1.y); ap[6]=pk2(av1.z); ap[7]=pk2(av1.w);
#pragma unroll
            for (int i=0;i<8;i++){
                fma2(acc2[i][0], ap[i], bp.x);
                fma2(acc2[i][1], ap[i], bp.y);
            }
        }
        __syncthreads();
        if (t+1 < nt){
            int nb = (t+1)&1;
            As[nb][ak+0][ar]=a0.x; As[nb][ak+1][ar]=a0.y; As[nb][ak+2][ar]=a0.z; As[nb][ak+3][ar]=a0.w;
            As[nb][ak+4][ar]=a1.x; As[nb][ak+5][ar]=a1.y; As[nb][ak+6][ar]=a1.z; As[nb][ak+7][ar]=a1.w;
            *(float4*)&Bs[nb][bk][bc]   = b0;
            *(float4*)&Bs[nb][bk][bc+4] = b1;
            __syncthreads();
        }
    }
    int cbase = col0 + tx*4;
    float bx=0.f,by=0.f,bz=0.f,bw=0.f;
    if (bias){ bx=bias[cbase]; by=bias[cbase+1]; bz=bias[cbase+2]; bw=bias[cbase+3]; }
#pragma unroll
    for (int i=0;i<8;i++){
        int r = row0 + ty*8 + i;
        size_t idx = (size_t)r*N + cbase;
        float2 p0 = upk(acc2[i][0]);
        float2 p1 = upk(acc2[i][1]);
        float4 v;
        v.x = p0.x+bx; v.y = p0.y+by; v.z = p1.x+bz; v.w = p1.y+bw;
        if (addC){
            float4 o = *(const float4*)&C[idx];
            v.x+=o.x; v.y+=o.y; v.z+=o.z; v.w+=o.w;
        }
        *(float4*)&C[idx] = v;
    }
}

// ---------------- conv + silu: 4 rows per thread ----------------
__global__ __launch_bounds__(128)
void conv_silu_kernel(const float* __restrict__ cw,
                      const float* __restrict__ cb){
    int c = blockIdx.x*128 + threadIdx.x;
    int r0 = blockIdx.y*4;
    int l0 = r0 & (Lseq-1);
    float w0 = cw[0*XBCd + c], w1 = cw[1*XBCd + c];
    float w2 = cw[2*XBCd + c], w3 = cw[3*XBCd + c];
    float bz = cb[c];
    float buf[7];
#pragma unroll
    for (int i = 0; i < 7; i++){
        int lsrc = l0 + i - 3;
        buf[i] = (lsrc >= 0) ? g_zx[(size_t)(r0 + i - 3)*DIPd + DI + c] : 0.f;
    }
#pragma unroll
    for (int j = 0; j < 4; j++){
        float acc = bz + buf[j]*w0 + buf[j+1]*w1 + buf[j+2]*w2 + buf[j+3]*w3;
        g_xbc[(size_t)(r0+j)*XBCd + c] = siluf(acc);
    }
}

// ---------------- fused dt softplus + warp-shuffle cumsum ----------------
__global__ __launch_bounds__(1024)
void dtcum_kernel(const float* __restrict__ dt_bias,
                  const float* __restrict__ A_log){
    __shared__ float wsum[32];
    int bh = blockIdx.x; int b = bh>>3, h = bh&7;
    int l = threadIdx.x;
    int wid = l >> 5, lane = l & 31;
    float raw = g_zx[(size_t)(b*Lseq+l)*DIPd + DI + XBCd + h] + dt_bias[h];
    float dtv = (raw > 20.f) ? raw : log1pf(expf(raw));
    g_dt[(size_t)bh*Lseq + l] = dtv;
    float v = dtv * (-expf(A_log[h]));
#pragma unroll
    for (int off=1; off<32; off<<=1){
        float n = __shfl_up_sync(0xffffffffu, v, off);
        if (lane >= off) v += n;
    }
    if (lane == 31) wsum[wid] = v;
    __syncthreads();
    if (wid == 0){
        float s = wsum[lane];
#pragma unroll
        for (int off=1; off<32; off<<=1){
            float n = __shfl_up_sync(0xffffffffu, s, off);
            if (lane >= off) s += n;
        }
        wsum[lane] = s;
    }
    __syncthreads();
    if (wid > 0) v += wsum[wid-1];
    g_cA[(size_t)bh*Lseq + l] = v;
    if ((l & 63) == 63) g_E[bh*NCH + (l>>6)] = v;
}

// ---------------- chunk state contribution ----------------
__global__ __launch_bounds__(128)
void mstate_kernel(){
    __shared__ float Ws[64*68];
    __shared__ float Xs[64*68];
    __shared__ float wsv[64];
    int c = blockIdx.x, h = blockIdx.y, b = blockIdx.z;
    int bh = b*Hh + h;
    int tid = threadIdx.x;
    int ty = tid>>4, tx = tid&15;
    size_t rowc = (size_t)(b*Lseq + c*64);
    if (tid < 64){
        float Ec = g_E[bh*NCH + c];
        wsv[tid] = expf(Ec - g_cA[(size_t)bh*Lseq + c*64 + tid]) * g_dt[(size_t)bh*Lseq + c*64 + tid];
    }
    __syncthreads();
#pragma unroll
    for (int cc=0; cc<8; cc++){
        int idx = cc*128 + tid;
        int r = idx>>4, n4 = (idx&15)*4;
        float w = wsv[r];
        float4 bv = *(const float4*)&g_xbc[(rowc+r)*XBCd + DI + n4];
        bv.x *= w; bv.y *= w; bv.z *= w; bv.w *= w;
        *(float4*)&Ws[r*68 + n4] = bv;
        float4 xv = *(const float4*)&g_xbc[(rowc+r)*XBCd + h*HDm + n4];
        *(float4*)&Xs[r*68 + n4] = xv;
    }
    __syncthreads();
    u64 acc2[8][2];
#pragma unroll
    for (int i=0;i<8;i++){ acc2[i][0]=0ULL; acc2[i][1]=0ULL; }
#pragma unroll 8
    for (int s=0;s<64;s++){
        float4 a0 = *(const float4*)&Ws[s*68 + ty*8];
        float4 a1 = *(const float4*)&Ws[s*68 + ty*8 + 4];
        ulonglong2 xp = *(const ulonglong2*)&Xs[s*68 + tx*4];
        u64 ap[8];
        ap[0]=pk2(a0.x); ap[1]=pk2(a0.y); ap[2]=pk2(a0.z); ap[3]=pk2(a0.w);
        ap[4]=pk2(a1.x); ap[5]=pk2(a1.y); ap[6]=pk2(a1.z); ap[7]=pk2(a1.w);
#pragma unroll
        for (int i=0;i<8;i++){
            fma2(acc2[i][0], ap[i], xp.x);
            fma2(acc2[i][1], ap[i], xp.y);
        }
    }
    float* G = g_G + ((size_t)bh*NCH + c)*4096;
#pragma unroll
    for (int i=0;i<8;i++){
        float2 p0 = upk(acc2[i][0]);
        float2 p1 = upk(acc2[i][1]);
        float4 v = make_float4(p0.x,p0.y,p1.x,p1.y);
        *(float4*)&G[(ty*8+i)*64 + tx*4] = v;
    }
}

// ---------------- sequential state scan (512 thr) ----------------
__global__ __launch_bounds__(512)
void mscan_kernel(){
    int bh = blockIdx.x;
    int tid = threadIdx.x;
    const float* E = g_E + bh*NCH;
    float hreg[8];
#pragma unroll
    for (int k=0;k<8;k++) hreg[k]=0.f;
    for (int c=1;c<NCH;c++){
        float d = (c>=2) ? expf(E[c-1]-E[c-2]) : 0.f;
        const float* G = g_G + ((size_t)bh*NCH + (c-1))*4096;
        float* H = g_Hst + ((size_t)bh*NCH + c)*4096;
#pragma unroll
        for (int k=0;k<8;k++){
            int e = tid + k*512;
            float g = G[e];
            hreg[k] = (c==1) ? g : fmaf(d, hreg[k], g);
            H[e] = hreg[k];
        }
    }
}

// ---------------- chunked Mamba2 output ----------------
#define MSMEM ((3*64*68 + 4*64)*4)
__global__ __launch_bounds__(128)
void mamba_kernel(const float* __restrict__ Dvec){
    extern __shared__ float smf[];
    float* CtT = smf;
    float* BsS = CtT + 64*68;
    float* XsH = BsS + 64*68;
    float* cAt = XsH + 64*68;
    float* dss = cAt + 64;
    float* qv  = dss + 64;
    int c = blockIdx.x, h = blockIdx.y, b = blockIdx.z;
    int bh = b*Hh + h;
    int tid = threadIdx.x;
    int ty = tid>>4, tx = tid&15;
    size_t rowt = (size_t)(b*Lseq + c*64);

#pragma unroll
    for (int cc=0; cc<8; cc++){
        int idx = cc*128 + tid;
        int r = idx>>4, n4 = (idx&15)*4;
        float4 v = *(const float4*)&g_xbc[(rowt + r)*XBCd + DI + DSm + n4];
        CtT[(n4+0)*68 + r] = v.x;
        CtT[(n4+1)*68 + r] = v.y;
        CtT[(n4+2)*68 + r] = v.z;
        CtT[(n4+3)*68 + r] = v.w;
        float4 bv = *(const float4*)&g_xbc[(rowt + r)*XBCd + DI + n4];
        BsS[(n4+0)*68 + r] = bv.x;
        BsS[(n4+1)*68 + r] = bv.y;
        BsS[(n4+2)*68 + r] = bv.z;
        BsS[(n4+3)*68 + r] = bv.w;
        float4 xv = *(const float4*)&g_xbc[(rowt + r)*XBCd + h*HDm + n4];
        *(float4*)&XsH[r*68 + n4] = xv;
    }
    if (tid < 64){
        float ca = g_cA[(size_t)bh*Lseq + c*64 + tid];
        cAt[tid] = ca;
        dss[tid] = g_dt[(size_t)bh*Lseq + c*64 + tid];
        qv[tid]  = (c > 0) ? expf(ca - g_E[bh*NCH + c - 1]) : 0.f;
    }
    __syncthreads();

    u64 cb2[8][2];
#pragma unroll
    for (int i=0;i<8;i++){ cb2[i][0]=0ULL; cb2[i][1]=0ULL; }
#pragma unroll 8
    for (int n=0;n<64;n++){
        float4 a0 = *(const float4*)&CtT[n*68 + ty*8];
        float4 a1 = *(const float4*)&CtT[n*68 + ty*8 + 4];
        ulonglong2 bp = *(const ulonglong2*)&BsS[n*68 + tx*4];
        u64 ap[8];
        ap[0]=pk2(a0.x); ap[1]=pk2(a0.y); ap[2]=pk2(a0.z); ap[3]=pk2(a0.w);
        ap[4]=pk2(a1.x); ap[5]=pk2(a1.y); ap[6]=pk2(a1.z); ap[7]=pk2(a1.w);
#pragma unroll
        for (int i=0;i<8;i++){
            fma2(cb2[i][0], ap[i], bp.x);
            fma2(cb2[i][1], ap[i], bp.y);
        }
    }
    __syncthreads();
    float d[8][4];
#pragma unroll
    for (int i=0;i<8;i++){
        int t = ty*8+i;
        float ca = cAt[t];
        float2 p0 = upk(cb2[i][0]);
        float2 p1 = upk(cb2[i][1]);
        float cbv[4] = {p0.x, p0.y, p1.x, p1.y};
#pragma unroll
        for (int j=0;j<4;j++){
            int s = tx*4+j;
            float v = 0.f;
            if (s <= t) v = expf(ca - cAt[s]) * cbv[j] * dss[s];
            d[i][j] = v;
        }
    }
#pragma unroll
    for (int j=0;j<4;j++){
        int s = tx*4+j;
        float4 v0 = make_float4(d[0][j],d[1][j],d[2][j],d[3][j]);
        float4 v1 = make_float4(d[4][j],d[5][j],d[6][j],d[7][j]);
        *(float4*)&BsS[s*68 + ty*8]   = v0;
        *(float4*)&BsS[s*68 + ty*8+4] = v1;
    }
    __syncthreads();
    u64 yacc2[8][2];
#pragma unroll
    for (int i=0;i<8;i++){ yacc2[i][0]=0ULL; yacc2[i][1]=0ULL; }
#pragma unroll 8
    for (int s=0;s<64;s++){
        float4 a0 = *(const float4*)&BsS[s*68 + ty*8];
        float4 a1 = *(const float4*)&BsS[s*68 + ty*8 + 4];
        ulonglong2 xp = *(const ulonglong2*)&XsH[s*68 + tx*4];
        u64 ap[8];
        ap[0]=pk2(a0.x); ap[1]=pk2(a0.y); ap[2]=pk2(a0.z); ap[3]=pk2(a0.w);
        ap[4]=pk2(a1.x); ap[5]=pk2(a1.y); ap[6]=pk2(a1.z); ap[7]=pk2(a1.w);
#pragma unroll
        for (int i=0;i<8;i++){
            fma2(yacc2[i][0], ap[i], xp.x);
            fma2(yacc2[i][1], ap[i], xp.y);
        }
    }
    __syncthreads();
    u64 zacc2[8][2];
#pragma unroll
    for (int i=0;i<8;i++){ zacc2[i][0]=0ULL; zacc2[i][1]=0ULL; }
    if (c > 0){
        const float* H = g_Hst + ((size_t)bh*NCH + c)*4096;
#pragma unroll
        for (int cc=0; cc<8; cc++){
            int idx = cc*128 + tid;
            int n = idx>>4, p4 = (idx&15)*4;
            float4 hv = *(const float4*)&H[n*64 + p4];
            *(float4*)&XsH[n*68 + p4] = hv;
        }
        __syncthreads();
#pragma unroll 8
        for (int n=0;n<64;n++){
            float4 a0 = *(const float4*)&CtT[n*68 + ty*8];
            float4 a1 = *(const float4*)&CtT[n*68 + ty*8 + 4];
            ulonglong2 hp = *(const ulonglong2*)&XsH[n*68 + tx*4];
            u64 ap[8];
            ap[0]=pk2(a0.x); ap[1]=pk2(a0.y); ap[2]=pk2(a0.z); ap[3]=pk2(a0.w);
            ap[4]=pk2(a1.x); ap[5]=pk2(a1.y); ap[6]=pk2(a1.z); ap[7]=pk2(a1.w);
#pragma unroll
            for (int i=0;i<8;i++){
                fma2(zacc2[i][0], ap[i], hp.x);
                fma2(zacc2[i][1], ap[i], hp.y);
            }
        }
    }
    float Dh = Dvec[h];
#pragma unroll
    for (int i=0;i<8;i++){
        int t = ty*8+i;
        float q = qv[t];
        float4 xv = *(const float4*)&g_xbc[(rowt+t)*XBCd + h*HDm + tx*4];
        float2 p0 = upk(yacc2[i][0]);
        float2 p1 = upk(yacc2[i][1]);
        float2 z0 = upk(zacc2[i][0]);
        float2 z1 = upk(zacc2[i][1]);
        float4 o;
        o.x = p0.x + q*z0.x + Dh*xv.x;
        o.y = p0.y + q*z0.y + Dh*xv.y;
        o.z = p1.x + q*z1.x + Dh*xv.z;
        o.w = p1.y + q*z1.y + Dh*xv.w;
        *(float4*)&g_y[(rowt+t)*DI + h*HDm + tx*4] = o;
    }
}

// ---------------- gated RMS norm: one warp per row (DI=512) ----------------
__global__ __launch_bounds__(256)
void gated_rms_warp(const float* __restrict__ nw){
    int wr = threadIdx.x >> 5, lane = threadIdx.x & 31;
    int row = blockIdx.x*8 + wr;
    float* Yr = g_y + (size_t)row*DI;
    const float* Zr = g_zx + (size_t)row*DIPd;
    float gg[16];
    float q = 0.f;
#pragma unroll
    for (int c=0;c<4;c++){
        int col = lane*4 + c*128;
        float4 yv = *(const float4*)(Yr + col);
        float4 zv = *(const float4*)(Zr + col);
        float g0 = yv.x * siluf(zv.x);
        float g1 = yv.y * siluf(zv.y);
        float g2 = yv.z * siluf(zv.z);
        float g3 = yv.w * siluf(zv.w);
        gg[c*4+0]=g0; gg[c*4+1]=g1; gg[c*4+2]=g2; gg[c*4+3]=g3;
        q += g0*g0 + g1*g1 + g2*g2 + g3*g3;
    }
#pragma unroll
    for (int off=16; off; off>>=1) q += __shfl_xor_sync(0xffffffffu, q, off);
    float scale = rsqrtf(q*(1.f/DI) + 1e-5f);
#pragma unroll
    for (int c=0;c<4;c++){
        int col = lane*4 + c*128;
        float4 wv = *(const float4*)(nw + col);
        float4 o;
        o.x = gg[c*4+0]*scale*wv.x;
        o.y = gg[c*4+1]*scale*wv.y;
        o.z = gg[c*4+2]*scale*wv.z;
        o.w = gg[c*4+3]*scale*wv.w;
        *(float4*)(Yr + col) = o;
    }
}

// ---------------- fused flash attention (non-causal, HD=64) ----------------
__global__ __launch_bounds__(128)
void flash_attn_kernel(){
    __shared__ float QT[64*68];
    __shared__ float KT[64*68];
    __shared__ float Vs[64*68];
    __shared__ float PT[64*68];
    int tt = blockIdx.x, h = blockIdx.y, b = blockIdx.z;
    int tid = threadIdx.x;
    int ty = tid>>4, tx = tid&15;

#pragma unroll
    for (int c=0;c<8;c++){
        int idx = c*128 + tid;
        int r = idx>>4, p4 = (idx&15)*4;
        float4 q = *(const float4*)&g_qkv[(size_t)(b*Lseq + tt*64 + r)*(3*Dm) + h*AHDd + p4];
        QT[(p4+0)*68 + r] = q.x*0.125f;
        QT[(p4+1)*68 + r] = q.y*0.125f;
        QT[(p4+2)*68 + r] = q.z*0.125f;
        QT[(p4+3)*68 + r] = q.w*0.125f;
    }

    float m[8], l[8];
    u64 oacc[8][2];
#pragma unroll
    for (int i=0;i<8;i++){ m[i] = -1e30f; l[i] = 0.f; oacc[i][0]=0ULL; oacc[i][1]=0ULL; }

    for (int st=0; st<16; st++){
        __syncthreads();
#pragma unroll
        for (int c=0;c<8;c++){
            int idx = c*128 + tid;
            int r = idx>>4, p4 = (idx&15)*4;
            float4 k = *(const float4*)&g_qkv[(size_t)(b*Lseq + st*64 + r)*(3*Dm) + Dm + h*AHDd + p4];
            KT[(p4+0)*68 + r] = k.x;
            KT[(p4+1)*68 + r] = k.y;
            KT[(p4+2)*68 + r] = k.z;
            KT[(p4+3)*68 + r] = k.w;
            float4 vv = *(const float4*)&g_qkv[(size_t)(b*Lseq + st*64 + r)*(3*Dm) + 2*Dm + h*AHDd + p4];
            *(float4*)&Vs[r*68 + p4] = vv;
        }
        __syncthreads();
        u64 sacc[8][2];
#pragma unroll
        for (int i=0;i<8;i++){ sacc[i][0]=0ULL; sacc[i][1]=0ULL; }
#pragma unroll 8
        for (int p=0;p<64;p++){
            float4 a0 = *(const float4*)&QT[p*68 + ty*8];
            float4 a1 = *(const float4*)&QT[p*68 + ty*8 + 4];
            ulonglong2 bp = *(const ulonglong2*)&KT[p*68 + tx*4];
            u64 ap[8];
            ap[0]=pk2(a0.x); ap[1]=pk2(a0.y); ap[2]=pk2(a0.z); ap[3]=pk2(a0.w);
            ap[4]=pk2(a1.x); ap[5]=pk2(a1.y); ap[6]=pk2(a1.z); ap[7]=pk2(a1.w);
#pragma unroll
            for (int i=0;i<8;i++){
                fma2(sacc[i][0], ap[i], bp.x);
                fma2(sacc[i][1], ap[i], bp.y);
            }
        }
        float pbuf[8][4];
#pragma unroll
        for (int i=0;i<8;i++){
            float2 s0 = upk(sacc[i][0]);
            float2 s1 = upk(sacc[i][1]);
            float sv[4] = {s0.x, s0.y, s1.x, s1.y};
            float mx = fmaxf(fmaxf(sv[0],sv[1]), fmaxf(sv[2],sv[3]));
#pragma unroll
            for (int off=8; off; off>>=1)
                mx = fmaxf(mx, __shfl_xor_sync(0xffffffffu, mx, off, 16));
            float mnew = fmaxf(m[i], mx);
            float scale = expf(m[i] - mnew);
            float psum = 0.f;
#pragma unroll
            for (int j=0;j<4;j++){ pbuf[i][j] = expf(sv[j] - mnew); psum += pbuf[i][j]; }
#pragma unroll
            for (int off=8; off; off>>=1)
                psum += __shfl_xor_sync(0xffffffffu, psum, off, 16);
            l[i] = l[i]*scale + psum;
            m[i] = mnew;
            float2 q0 = upk(oacc[i][0]);
            float2 q1 = upk(oacc[i][1]);
            oacc[i][0] = pk2ab(q0.x*scale, q0.y*scale);
            oacc[i][1] = pk2ab(q1.x*scale, q1.y*scale);
        }
#pragma unroll
        for (int j=0;j<4;j++){
            int s = tx*4+j;
            *(float4*)&PT[s*68 + ty*8]   = make_float4(pbuf[0][j],pbuf[1][j],pbuf[2][j],pbuf[3][j]);
            *(float4*)&PT[s*68 + ty*8+4] = make_float4(pbuf[4][j],pbuf[5][j],pbuf[6][j],pbuf[7][j]);
        }
        __syncthreads();
#pragma unroll 8
        for (int s=0;s<64;s++){
            float4 a0 = *(const float4*)&PT[s*68 + ty*8];
            float4 a1 = *(const float4*)&PT[s*68 + ty*8 + 4];
            ulonglong2 xp = *(const ulonglong2*)&Vs[s*68 + tx*4];
            u64 ap[8];
            ap[0]=pk2(a0.x); ap[1]=pk2(a0.y); ap[2]=pk2(a0.z); ap[3]=pk2(a0.w);
            ap[4]=pk2(a1.x); ap[5]=pk2(a1.y); ap[6]=pk2(a1.z); ap[7]=pk2(a1.w);
#pragma unroll
            for (int i=0;i<8;i++){
                fma2(oacc[i][0], ap[i], xp.x);
                fma2(oacc[i][1], ap[i], xp.y);
            }
        }
    }
#pragma unroll
    for (int i=0;i<8;i++){
        float inv = 1.f / l[i];
        float2 p0 = upk(oacc[i][0]);
        float2 p1 = upk(oacc[i][1]);
        float4 v = make_float4(p0.x*inv, p0.y*inv, p1.x*inv, p1.y*inv);
        *(float4*)&g_attnO[(size_t)(b*Lseq + tt*64 + ty*8+i)*Dm + h*AHDd + tx*4] = v;
    }
}

// ---------------- mean over L ----------------
__global__ __launch_bounds__(1024)
void mean_kernel(){
    __shared__ float part[4][256];
    int b = blockIdx.x;
    int t = threadIdx.x;
    int d = t & 255, lg = t >> 8;
    float s = 0.f;
    for (int l = lg; l < Lseq; l += 4) s += g_lnbuf[(size_t)(b*Lseq + l)*Dm + d];
    part[lg][d] = s;
    __syncthreads();
    if (t < 256) g_hm[b*Dm + t] = (part[0][t]+part[1][t]+part[2][t]+part[3][t])*(1.f/Lseq);
}

// ---------------- output heads ----------------
__global__ void head_kernel(const float* __restrict__ dw, const float* __restrict__ db,
                            const float* __restrict__ rw, const float* __restrict__ rb,
                            float* __restrict__ out){
    int t = threadIdx.x; if (t >= 24) return;
    int which = t/12; int b = (t%12)/3; int j = t%3;
    const float* W  = which ? rw : dw;
    const float* bs = which ? rb : db;
    float acc = bs[j];
    for (int d = 0; d < Dm; d++) acc += g_hm[b*Dm + d]*W[d*3 + j];
    out[which*12 + b*3 + j] = acc;
}

// ---------------- launch ----------------
extern "C" void kernel_launch(void* const* d_in, const int* in_sizes, int n_in,
                              void* d_out, int out_size){
    const float* x          = (const float*)d_in[0];
    const float* pos_emb    = (const float*)d_in[1];
    const float* in_w       = (const float*)d_in[2];
    const float* in_b       = (const float*)d_in[3];
    const float* ln1_w      = (const float*)d_in[4];
    const float* ln1_b      = (const float*)d_in[5];
    const float* ssm_in_w   = (const float*)d_in[6];
    const float* ssm_conv_w = (const float*)d_in[7];
    const float* ssm_conv_b = (const float*)d_in[8];
    const float* ssm_dt_bias= (const float*)d_in[9];
    const float* ssm_A_log  = (const float*)d_in[10];
    const float* ssm_D      = (const float*)d_in[11];
    const float* ssm_norm_w = (const float*)d_in[12];
    const float* ssm_out_w  = (const float*)d_in[13];
    const float* ln2_w      = (const float*)d_in[14];
    const float* ln2_b      = (const float*)d_in[15];
    const float* fc1_w      = (const float*)d_in[16];
    const float* fc1_b      = (const float*)d_in[17];
    const float* fc2_w      = (const float*)d_in[18];
    const float* fc2_b      = (const float*)d_in[19];
    const float* attn_ln_w  = (const float*)d_in[20];
    const float* attn_ln_b  = (const float*)d_in[21];
    const float* attn_qkv_w = (const float*)d_in[22];
    const float* attn_qkv_b = (const float*)d_in[23];
    const float* attn_out_w = (const float*)d_in[24];
    const float* attn_out_b = (const float*)d_in[25];
    const float* norm_w     = (const float*)d_in[26];
    const float* norm_b     = (const float*)d_in[27];
    const float* dir_w      = (const float*)d_in[28];
    const float* dir_b      = (const float*)d_in[29];
    const float* reg_w      = (const float*)d_in[30];
    const float* reg_b      = (const float*)d_in[31];
    float* out = (float*)d_out;

    cudaFuncSetAttribute(mamba_kernel, cudaFuncAttributeMaxDynamicSharedMemorySize, MSMEM);

    float *ph, *pln, *pzx, *py, *pqkv, *pattnO, *pff2;
    cudaGetSymbolAddress((void**)&ph,     g_h);
    cudaGetSymbolAddress((void**)&pln,    g_lnbuf);
    cudaGetSymbolAddress((void**)&pzx,    g_zx);
    cudaGetSymbolAddress((void**)&py,     g_y);
    cudaGetSymbolAddress((void**)&pqkv,   g_qkv);
    cudaGetSymbolAddress((void**)&pattnO, g_attnO);
    cudaGetSymbolAddress((void**)&pff2,   g_ff2);

    embed_kernel<<<ROWS, 256>>>(x, in_w, in_b, pos_emb);

    for (int i = 0; i < NLAY; i++){
        // ---- Mamba2 branch ----
        ln_warp<<<ROWS/8, 256>>>(ph, ln1_w + i*Dm, ln1_b + i*Dm, pln);
        gemm64n<<<dim3((DIPd+63)/64, ROWS/128), 256>>>(
            pln, ssm_in_w + (size_t)i*Dm*DIPd, nullptr, pzx, 256, DIPd, 0);
        conv_silu_kernel<<<dim3(XBCd/128, ROWS/4), 128>>>(
            ssm_conv_w + (size_t)i*Kc*XBCd, ssm_conv_b + (size_t)i*XBCd);
        dtcum_kernel<<<Bb*Hh, 1024>>>(ssm_dt_bias + i*Hh, ssm_A_log + i*Hh);
        mstate_kernel<<<dim3(NCH, Hh, Bb), 128>>>();
        mscan_kernel<<<Bb*Hh, 512>>>();
        mamba_kernel<<<dim3(NCH, Hh, Bb), 128, MSMEM>>>(ssm_D + i*Hh);
        gated_rms_warp<<<ROWS/8, 256>>>(ssm_norm_w + (size_t)i*DI);
        gemm64x64<<<dim3(Dm/64, ROWS/64), 128>>>(
            py, ssm_out_w + (size_t)i*DI*Dm, nullptr, ph, 512, Dm, 1);

        // ---- attention (odd layers) ----
        if (i & 1){
            int j = i >> 1;
            ln_warp<<<ROWS/8, 256>>>(ph, attn_ln_w + j*Dm, attn_ln_b + j*Dm, pln);
            gemm64n<<<dim3(3*Dm/64, ROWS/128), 256>>>(
                pln, attn_qkv_w + (size_t)j*Dm*3*Dm, attn_qkv_b + (size_t)j*3*Dm, pqkv, 256, 3*Dm, 0);
            flash_attn_kernel<<<dim3(16, AHn, Bb), 128>>>();
            gemm64x64<<<dim3(Dm/64, ROWS/64), 128>>>(
                pattnO, attn_out_w + (size_t)j*Dm*Dm, attn_out_b + (size_t)j*Dm, ph, 256, Dm, 1);
        }

        // ---- gMLP ----
        ln_warp<<<ROWS/8, 256>>>(ph, ln2_w + i*Dm, ln2_b + i*Dm, pln);
        gemm_fc1<<<dim3(DFFd/32, ROWS/128), 256>>>(
            pln, fc1_w + (size_t)i*Dm*2*DFFd, fc1_b + (size_t)i*2*DFFd, pff2, 256);
        gemm64x64<<<dim3(Dm/64, ROWS/64), 128>>>(
            pff2, fc2_w + (size_t)i*DFFd*Dm, fc2_b + (size_t)i*Dm, ph, 512, Dm, 1);
    }

    // ---- final norm, mean, heads ----
    ln_warp<<<ROWS/8, 256>>>(ph, norm_w, norm_b, pln);
    mean_kernel<<<Bb, 1024>>>();
    head_kernel<<<1, 32>>>(dir_w, dir_b, reg_w, reg_b, out);
}

// round 13
// speedup vs baseline: 1.0733x; 1.0733x over previous
#include <cuda_runtime.h>
#include <math.h>
#include <stdint.h>

// ---------------- problem constants ----------------
#define Bb 4
#define Lseq 1024
#define INDIM 46
#define Dm 256
#define DSm 64
#define Kc 4
#define NLAY 4
#define DI 512
#define HDm 64
#define Hh 8
#define XBCd 640
#define DIPd 1160
#define DFFd 512
#define AHn 4
#define AHDd 64
#define ROWS (Bb*Lseq)
#define NCH 16

typedef unsigned long long u64;

// ---------------- device scratch ----------------
__device__ float g_h[ROWS*Dm];
__device__ float g_lnbuf[ROWS*Dm];
__device__ float g_zx[ROWS*DIPd];
__device__ float g_xbc[ROWS*XBCd];
__device__ float g_dt[Bb*Hh*Lseq];
__device__ float g_cA[Bb*Hh*Lseq];
__device__ float g_E[Bb*Hh*NCH];
__device__ float g_G[(size_t)Bb*Hh*NCH*4096];
__device__ float g_Hst[(size_t)Bb*Hh*NCH*4096];
__device__ float g_y[ROWS*DI];
__device__ float g_qkv[ROWS*3*Dm];
__device__ float g_attnO[ROWS*Dm];
__device__ float g_ff2[ROWS*DFFd];
__device__ float g_hm[Bb*Dm];

__device__ __forceinline__ float siluf(float x){ return x / (1.f + expf(-x)); }
__device__ __forceinline__ float geluf(float x){ return 0.5f*x*(1.f + erff(x*0.70710678118654752f)); }

// ---------------- packed fp32x2 helpers ----------------
__device__ __forceinline__ u64 pk2(float x){
    u64 r; asm("mov.b64 %0, {%1, %1};" : "=l"(r) : "f"(x)); return r;
}
__device__ __forceinline__ u64 pk2ab(float a, float b){
    u64 r; asm("mov.b64 %0, {%1, %2};" : "=l"(r) : "f"(a), "f"(b)); return r;
}
__device__ __forceinline__ void fma2(u64 &d, u64 a, u64 b){
    asm("fma.rn.f32x2 %0, %1, %2, %0;" : "+l"(d) : "l"(a), "l"(b));
}
__device__ __forceinline__ float2 upk(u64 v){
    float2 f; asm("mov.b64 {%0, %1}, %2;" : "=f"(f.x), "=f"(f.y) : "l"(v)); return f;
}

// ---------------- embed ----------------
__global__ void embed_kernel(const float* __restrict__ x,
                             const float* __restrict__ in_w,
                             const float* __restrict__ in_b,
                             const float* __restrict__ pos){
    int row = blockIdx.x;
    int d = threadIdx.x;
    __shared__ float xr[INDIM];
    if (d < INDIM) xr[d] = x[(size_t)row*INDIM + d];
    __syncthreads();
    float acc = in_b[d];
#pragma unroll
    for (int i = 0; i < INDIM; i++) acc += xr[i]*in_w[i*Dm + d];
    int l = row & (Lseq-1);
    g_h[(size_t)row*Dm + d] = acc + pos[(size_t)l*Dm + d];
}

// ---------------- layernorm: one warp per row (D=256) ----------------
__global__ __launch_bounds__(256)
void ln_warp(const float* __restrict__ X,
             const float* __restrict__ w,
             const float* __restrict__ b,
             float* __restrict__ out){
    int wr = threadIdx.x >> 5, lane = threadIdx.x & 31;
    int row = blockIdx.x*8 + wr;
    const float* Xr = X + (size_t)row*Dm;
    float4 v0 = *(const float4*)(Xr + lane*8);
    float4 v1 = *(const float4*)(Xr + lane*8 + 4);
    float s = v0.x+v0.y+v0.z+v0.w + v1.x+v1.y+v1.z+v1.w;
#pragma unroll
    for (int off=16; off; off>>=1) s += __shfl_xor_sync(0xffffffffu, s, off);
    float m = s*(1.f/Dm);
    float d0=v0.x-m, d1=v0.y-m, d2=v0.z-m, d3=v0.w-m;
    float d4=v1.x-m, d5=v1.y-m, d6=v1.z-m, d7=v1.w-m;
    float q = d0*d0+d1*d1+d2*d2+d3*d3+d4*d4+d5*d5+d6*d6+d7*d7;
#pragma unroll
    for (int off=16; off; off>>=1) q += __shfl_xor_sync(0xffffffffu, q, off);
    float rs = rsqrtf(q*(1.f/Dm) + 1e-5f);
    float4 w0 = *(const float4*)(w + lane*8);
    float4 w1 = *(const float4*)(w + lane*8 + 4);
    float4 b0 = *(const float4*)(b + lane*8);
    float4 b1 = *(const float4*)(b + lane*8 + 4);
    float4 o0, o1;
    o0.x = d0*rs*w0.x + b0.x; o0.y = d1*rs*w0.y + b0.y;
    o0.z = d2*rs*w0.z + b0.z; o0.w = d3*rs*w0.w + b0.w;
    o1.x = d4*rs*w1.x + b1.x; o1.y = d5*rs*w1.y + b1.y;
    o1.z = d6*rs*w1.z + b1.z; o1.w = d7*rs*w1.w + b1.w;
    *(float4*)(out + (size_t)row*Dm + lane*8)     = o0;
    *(float4*)(out + (size_t)row*Dm + lane*8 + 4) = o1;
}

// ---------------- SGEMM 128x64 tile, 8x4 micro, 256 thr, N-guarded ----------------
__global__ __launch_bounds__(256,2)
void gemm64n(const float* __restrict__ A, const float* __restrict__ W,
             const float* __restrict__ bias, float* __restrict__ C,
             int K, int N, int addC){
    __shared__ float As[2][16][128];
    __shared__ float Bs[2][16][64];
    int tid = threadIdx.x;
    int row0 = blockIdx.y*128, col0 = blockIdx.x*64;
    int ar = tid>>1, ak = (tid&1)*8;
    int bk = tid>>4, bc = (tid&15)*4;
    int ty = tid>>4, tx = tid&15;
    bool bok = (col0 + bc + 4 <= N);
    const float* Ap = A + (size_t)(row0+ar)*K + ak;
    float4 a0,a1,b0;
    a0 = *(const float4*)(Ap);
    a1 = *(const float4*)(Ap+4);
    b0 = make_float4(0.f,0.f,0.f,0.f);
    if (bok) b0 = *(const float4*)(W + (size_t)bk*N + col0+bc);
    int nt = K>>4;
    As[0][ak+0][ar]=a0.x; As[0][ak+1][ar]=a0.y; As[0][ak+2][ar]=a0.z; As[0][ak+3][ar]=a0.w;
    As[0][ak+4][ar]=a1.x; As[0][ak+5][ar]=a1.y; As[0][ak+6][ar]=a1.z; As[0][ak+7][ar]=a1.w;
    *(float4*)&Bs[0][bk][bc] = b0;
    __syncthreads();
    u64 acc2[8][2];
#pragma unroll
    for (int i=0;i<8;i++){ acc2[i][0]=0ULL; acc2[i][1]=0ULL; }
    for (int t=0; t<nt; t++){
        if (t+1 < nt){
            int k0 = (t+1)*16;
            a0 = *(const float4*)(Ap + k0);
            a1 = *(const float4*)(Ap + k0 + 4);
            b0 = make_float4(0.f,0.f,0.f,0.f);
            if (bok) b0 = *(const float4*)(W + (size_t)(k0+bk)*N + col0+bc);
        }
        int buf = t&1;
#pragma unroll
        for (int k=0;k<16;k++){
            float4 av0 = *(const float4*)&As[buf][k][ty*8];
            float4 av1 = *(const float4*)&As[buf][k][ty*8+4];
            ulonglong2 bp = *(const ulonglong2*)&Bs[buf][k][tx*4];
            u64 ap[8];
            ap[0]=pk2(av0.x); ap[1]=pk2(av0.y); ap[2]=pk2(av0.z); ap[3]=pk2(av0.w);
            ap[4]=pk2(av1.x); ap[5]=pk2(av1.y); ap[6]=pk2(av1.z); ap[7]=pk2(av1.w);
#pragma unroll
            for (int i=0;i<8;i++){
                fma2(acc2[i][0], ap[i], bp.x);
                fma2(acc2[i][1], ap[i], bp.y);
            }
        }
        __syncthreads();
        if (t+1 < nt){
            int nb = (t+1)&1;
            As[nb][ak+0][ar]=a0.x; As[nb][ak+1][ar]=a0.y; As[nb][ak+2][ar]=a0.z; As[nb][ak+3][ar]=a0.w;
            As[nb][ak+4][ar]=a1.x; As[nb][ak+5][ar]=a1.y; As[nb][ak+6][ar]=a1.z; As[nb][ak+7][ar]=a1.w;
            *(float4*)&Bs[nb][bk][bc] = b0;
            __syncthreads();
        }
    }
    int cbase = col0 + tx*4;
    if (cbase + 4 <= N){
        float bx=0.f,by=0.f,bz=0.f,bw=0.f;
        if (bias){ bx=bias[cbase]; by=bias[cbase+1]; bz=bias[cbase+2]; bw=bias[cbase+3]; }
#pragma unroll
        for (int i=0;i<8;i++){
            int r = row0 + ty*8 + i;
            size_t idx = (size_t)r*N + cbase;
            float2 p0 = upk(acc2[i][0]);
            float2 p1 = upk(acc2[i][1]);
            float4 v;
            v.x = p0.x+bx; v.y = p0.y+by; v.z = p1.x+bz; v.w = p1.y+bw;
            if (addC){
                float4 o = *(const float4*)&C[idx];
                v.x+=o.x; v.y+=o.y; v.z+=o.z; v.w+=o.w;
            }
            *(float4*)&C[idx] = v;
        }
    }
}

// ---------------- fc1 GEMM with fused gelu-gate epilogue (R10 version) ----------------
__global__ __launch_bounds__(256,2)
void gemm_fc1(const float* __restrict__ A, const float* __restrict__ W,
              const float* __restrict__ bias, float* __restrict__ C, int K){
    __shared__ float As[2][16][128];
    __shared__ float Bs[2][16][128];
    int tid = threadIdx.x;
    int row0 = blockIdx.y*128, col0 = blockIdx.x*64;
    int ar = tid>>1, ak = (tid&1)*8;
    int bk = tid>>4, bn = (tid&15)*8;
    int bcol = (bn < 64) ? (col0 + bn) : (512 + col0 + bn - 64);
    int ty = tid>>4, tx = tid&15;
    const float* Ap = A + (size_t)(row0+ar)*K + ak;
    float4 a0,a1,b0,b1;
    a0 = *(const float4*)(Ap);
    a1 = *(const float4*)(Ap+4);
    b0 = *(const float4*)(W + (size_t)bk*1024 + bcol);
    b1 = *(const float4*)(W + (size_t)bk*1024 + bcol + 4);
    int nt = K>>4;
    As[0][ak+0][ar]=a0.x; As[0][ak+1][ar]=a0.y; As[0][ak+2][ar]=a0.z; As[0][ak+3][ar]=a0.w;
    As[0][ak+4][ar]=a1.x; As[0][ak+5][ar]=a1.y; As[0][ak+6][ar]=a1.z; As[0][ak+7][ar]=a1.w;
    *(float4*)&Bs[0][bk][bn]   = b0;
    *(float4*)&Bs[0][bk][bn+4] = b1;
    __syncthreads();
    u64 acc2[8][4];
#pragma unroll
    for (int i=0;i<8;i++)
#pragma unroll
        for (int j=0;j<4;j++) acc2[i][j]=0ULL;
    for (int t=0; t<nt; t++){
        if (t+1 < nt){
            int k0 = (t+1)*16;
            a0 = *(const float4*)(Ap + k0);
            a1 = *(const float4*)(Ap + k0 + 4);
            b0 = *(const float4*)(W + (size_t)(k0+bk)*1024 + bcol);
            b1 = *(const float4*)(W + (size_t)(k0+bk)*1024 + bcol + 4);
        }
        int buf = t&1;
#pragma unroll
        for (int k=0;k<16;k++){
            float4 av0 = *(const float4*)&As[buf][k][ty*8];
            float4 av1 = *(const float4*)&As[buf][k][ty*8+4];
            ulonglong2 bp0 = *(const ulonglong2*)&Bs[buf][k][tx*4];
            ulonglong2 bp1 = *(const ulonglong2*)&Bs[buf][k][64+tx*4];
            u64 ap[8];
            ap[0]=pk2(av0.x); ap[1]=pk2(av0.y); ap[2]=pk2(av0.z); ap[3]=pk2(av0.w);
            ap[4]=pk2(av1.x); ap[5]=pk2(av1.y); ap[6]=pk2(av1.z); ap[7]=pk2(av1.w);
#pragma unroll
            for (int i=0;i<8;i++){
                fma2(acc2[i][0], ap[i], bp0.x);
                fma2(acc2[i][1], ap[i], bp0.y);
                fma2(acc2[i][2], ap[i], bp1.x);
                fma2(acc2[i][3], ap[i], bp1.y);
            }
        }
        __syncthreads();
        if (t+1 < nt){
            int nb = (t+1)&1;
            As[nb][ak+0][ar]=a0.x; As[nb][ak+1][ar]=a0.y; As[nb][ak+2][ar]=a0.z; As[nb][ak+3][ar]=a0.w;
            As[nb][ak+4][ar]=a1.x; As[nb][ak+5][ar]=a1.y; As[nb][ak+6][ar]=a1.z; As[nb][ak+7][ar]=a1.w;
            *(float4*)&Bs[nb][bk][bn]   = b0;
            *(float4*)&Bs[nb][bk][bn+4] = b1;
            __syncthreads();
        }
    }
    int c1 = col0 + tx*4;
    float4 bv1 = *(const float4*)&bias[c1];
    float4 bv2 = *(const float4*)&bias[512 + c1];
#pragma unroll
    for (int i=0;i<8;i++){
        int r = row0 + ty*8 + i;
        float2 x10 = upk(acc2[i][0]);
        float2 x11 = upk(acc2[i][1]);
        float2 x20 = upk(acc2[i][2]);
        float2 x21 = upk(acc2[i][3]);
        float4 v;
        v.x = geluf(x10.x + bv1.x) * (x20.x + bv2.x);
        v.y = geluf(x10.y + bv1.y) * (x20.y + bv2.y);
        v.z = geluf(x11.x + bv1.z) * (x21.x + bv2.z);
        v.w = geluf(x11.y + bv1.w) * (x21.y + bv2.w);
        *(float4*)&C[(size_t)r*DFFd + c1] = v;
    }
}

// ---------------- SGEMM 64x64 tile (N=256 GEMMs) ----------------
__global__ __launch_bounds__(128)
void gemm64x64(const float* __restrict__ A, const float* __restrict__ W,
               const float* __restrict__ bias, float* __restrict__ C,
               int K, int N, int addC){
    __shared__ float As[2][16][64];
    __shared__ float Bs[2][16][64];
    int tid = threadIdx.x;
    int row0 = blockIdx.y*64, col0 = blockIdx.x*64;
    int ar = tid>>1, ak = (tid&1)*8;
    int bk = tid>>3, bc = (tid&7)*8;
    int ty = tid>>4, tx = tid&15;
    const float* Ap = A + (size_t)(row0+ar)*K + ak;
    float4 a0,a1,b0,b1;
    a0 = *(const float4*)(Ap);
    a1 = *(const float4*)(Ap+4);
    b0 = *(const float4*)(W + (size_t)bk*N + col0+bc);
    b1 = *(const float4*)(W + (size_t)bk*N + col0+bc+4);
    int nt = K>>4;
    As[0][ak+0][ar]=a0.x; As[0][ak+1][ar]=a0.y; As[0][ak+2][ar]=a0.z; As[0][ak+3][ar]=a0.w;
    As[0][ak+4][ar]=a1.x; As[0][ak+5][ar]=a1.y; As[0][ak+6][ar]=a1.z; As[0][ak+7][ar]=a1.w;
    *(float4*)&Bs[0][bk][bc]   = b0;
    *(float4*)&Bs[0][bk][bc+4] = b1;
    __syncthreads();
    u64 acc2[8][2];
#pragma unroll
    for (int i=0;i<8;i++){ acc2[i][0]=0ULL; acc2[i][1]=0ULL; }
    for (int t=0; t<nt; t++){
        if (t+1 < nt){
            int k0 = (t+1)*16;
            a0 = *(const float4*)(Ap + k0);
            a1 = *(const float4*)(Ap + k0 + 4);
            b0 = *(const float4*)(W + (size_t)(k0+bk)*N + col0+bc);
            b1 = *(const float4*)(W + (size_t)(k0+bk)*N + col0+bc+4);
        }
        int buf = t&1;
#pragma unroll
        for (int k=0;k<16;k++){
            float4 av0 = *(const float4*)&As[buf][k][ty*8];
            float4 av1 = *(const float4*)&As[buf][k][ty*8+4];
            ulonglong2 bp = *(const ulonglong2*)&Bs[buf][k][tx*4];
            u64 ap[8];
            ap[0]=pk2(av0.x); ap[1]=pk2(av0.y); ap[2]=pk2(av0.z); ap[3]=pk2(av0.w);
            ap[4]=pk2(av1.x); ap[5]=pk2(av1.y); ap[6]=pk2(av1.z); ap[7]=pk2(av1.w);
#pragma unroll
            for (int i=0;i<8;i++){
                fma2(acc2[i][0], ap[i], bp.x);
                fma2(acc2[i][1], ap[i], bp.y);
            }
        }
        __syncthreads();
        if (t+1 < nt){
            int nb = (t+1)&1;
            As[nb][ak+0][ar]=a0.x; As[nb][ak+1][ar]=a0.y; As[nb][ak+2][ar]=a0.z; As[nb][ak+3][ar]=a0.w;
            As[nb][ak+4][ar]=a1.x; As[nb][ak+5][ar]=a1.y; As[nb][ak+6][ar]=a1.z; As[nb][ak+7][ar]=a1.w;
            *(float4*)&Bs[nb][bk][bc]   = b0;
            *(float4*)&Bs[nb][bk][bc+4] = b1;
            __syncthreads();
        }
    }
    int cbase = col0 + tx*4;
    float bx=0.f,by=0.f,bz=0.f,bw=0.f;
    if (bias){ bx=bias[cbase]; by=bias[cbase+1]; bz=bias[cbase+2]; bw=bias[cbase+3]; }
#pragma unroll
    for (int i=0;i<8;i++){
        int r = row0 + ty*8 + i;
        size_t idx = (size_t)r*N + cbase;
        float2 p0 = upk(acc2[i][0]);
        float2 p1 = upk(acc2[i][1]);
        float4 v;
        v.x = p0.x+bx; v.y = p0.y+by; v.z = p1.x+bz; v.w = p1.y+bw;
        if (addC){
            float4 o = *(const float4*)&C[idx];
            v.x+=o.x; v.y+=o.y; v.z+=o.z; v.w+=o.w;
        }
        *(float4*)&C[idx] = v;
    }
}

// ---------------- conv + silu: 8 rows per thread, 11 loads feed 8 outputs ----------------
__global__ __launch_bounds__(128)
void conv_silu_kernel(const float* __restrict__ cw,
                      const float* __restrict__ cb){
    int c = blockIdx.x*128 + threadIdx.x;
    int r0 = blockIdx.y*8;
    int l0 = r0 & (Lseq-1);
    float w0 = cw[0*XBCd + c], w1 = cw[1*XBCd + c];
    float w2 = cw[2*XBCd + c], w3 = cw[3*XBCd + c];
    float bz = cb[c];
    float buf[11];
#pragma unroll
    for (int i = 0; i < 11; i++){
        int lsrc = l0 + i - 3;
        buf[i] = (lsrc >= 0) ? g_zx[(size_t)(r0 + i - 3)*DIPd + DI + c] : 0.f;
    }
#pragma unroll
    for (int j = 0; j < 8; j++){
        float acc = bz + buf[j]*w0 + buf[j+1]*w1 + buf[j+2]*w2 + buf[j+3]*w3;
        g_xbc[(size_t)(r0+j)*XBCd + c] = siluf(acc);
    }
}

// ---------------- fused dt softplus + warp-shuffle cumsum ----------------
__global__ __launch_bounds__(1024)
void dtcum_kernel(const float* __restrict__ dt_bias,
                  const float* __restrict__ A_log){
    __shared__ float wsum[32];
    int bh = blockIdx.x; int b = bh>>3, h = bh&7;
    int l = threadIdx.x;
    int wid = l >> 5, lane = l & 31;
    float raw = g_zx[(size_t)(b*Lseq+l)*DIPd + DI + XBCd + h] + dt_bias[h];
    float dtv = (raw > 20.f) ? raw : log1pf(expf(raw));
    g_dt[(size_t)bh*Lseq + l] = dtv;
    float v = dtv * (-expf(A_log[h]));
#pragma unroll
    for (int off=1; off<32; off<<=1){
        float n = __shfl_up_sync(0xffffffffu, v, off);
        if (lane >= off) v += n;
    }
    if (lane == 31) wsum[wid] = v;
    __syncthreads();
    if (wid == 0){
        float s = wsum[lane];
#pragma unroll
        for (int off=1; off<32; off<<=1){
            float n = __shfl_up_sync(0xffffffffu, s, off);
            if (lane >= off) s += n;
        }
        wsum[lane] = s;
    }
    __syncthreads();
    if (wid > 0) v += wsum[wid-1];
    g_cA[(size_t)bh*Lseq + l] = v;
    if ((l & 63) == 63) g_E[bh*NCH + (l>>6)] = v;
}

// ---------------- chunk state contribution ----------------
__global__ __launch_bounds__(128)
void mstate_kernel(){
    __shared__ float Ws[64*68];
    __shared__ float Xs[64*68];
    __shared__ float wsv[64];
    int c = blockIdx.x, h = blockIdx.y, b = blockIdx.z;
    int bh = b*Hh + h;
    int tid = threadIdx.x;
    int ty = tid>>4, tx = tid&15;
    size_t rowc = (size_t)(b*Lseq + c*64);
    if (tid < 64){
        float Ec = g_E[bh*NCH + c];
        wsv[tid] = expf(Ec - g_cA[(size_t)bh*Lseq + c*64 + tid]) * g_dt[(size_t)bh*Lseq + c*64 + tid];
    }
    __syncthreads();
#pragma unroll
    for (int cc=0; cc<8; cc++){
        int idx = cc*128 + tid;
        int r = idx>>4, n4 = (idx&15)*4;
        float w = wsv[r];
        float4 bv = *(const float4*)&g_xbc[(rowc+r)*XBCd + DI + n4];
        bv.x *= w; bv.y *= w; bv.z *= w; bv.w *= w;
        *(float4*)&Ws[r*68 + n4] = bv;
        float4 xv = *(const float4*)&g_xbc[(rowc+r)*XBCd + h*HDm + n4];
        *(float4*)&Xs[r*68 + n4] = xv;
    }
    __syncthreads();
    u64 acc2[8][2];
#pragma unroll
    for (int i=0;i<8;i++){ acc2[i][0]=0ULL; acc2[i][1]=0ULL; }
#pragma unroll 8
    for (int s=0;s<64;s++){
        float4 a0 = *(const float4*)&Ws[s*68 + ty*8];
        float4 a1 = *(const float4*)&Ws[s*68 + ty*8 + 4];
        ulonglong2 xp = *(const ulonglong2*)&Xs[s*68 + tx*4];
        u64 ap[8];
        ap[0]=pk2(a0.x); ap[1]=pk2(a0.y); ap[2]=pk2(a0.z); ap[3]=pk2(a0.w);
        ap[4]=pk2(a1.x); ap[5]=pk2(a1.y); ap[6]=pk2(a1.z); ap[7]=pk2(a1.w);
#pragma unroll
        for (int i=0;i<8;i++){
            fma2(acc2[i][0], ap[i], xp.x);
            fma2(acc2[i][1], ap[i], xp.y);
        }
    }
    float* G = g_G + ((size_t)bh*NCH + c)*4096;
#pragma unroll
    for (int i=0;i<8;i++){
        float2 p0 = upk(acc2[i][0]);
        float2 p1 = upk(acc2[i][1]);
        float4 v = make_float4(p0.x,p0.y,p1.x,p1.y);
        *(float4*)&G[(ty*8+i)*64 + tx*4] = v;
    }
}

// ---------------- sequential state scan (512 thr) ----------------
__global__ __launch_bounds__(512)
void mscan_kernel(){
    int bh = blockIdx.x;
    int tid = threadIdx.x;
    const float* E = g_E + bh*NCH;
    float hreg[8];
#pragma unroll
    for (int k=0;k<8;k++) hreg[k]=0.f;
    for (int c=1;c<NCH;c++){
        float d = (c>=2) ? expf(E[c-1]-E[c-2]) : 0.f;
        const float* G = g_G + ((size_t)bh*NCH + (c-1))*4096;
        float* H = g_Hst + ((size_t)bh*NCH + c)*4096;
#pragma unroll
        for (int k=0;k<8;k++){
            int e = tid + k*512;
            float g = G[e];
            hreg[k] = (c==1) ? g : fmaf(d, hreg[k], g);
            H[e] = hreg[k];
        }
    }
}

// ---------------- chunked Mamba2 output ----------------
#define MSMEM ((3*64*68 + 4*64)*4)
__global__ __launch_bounds__(128)
void mamba_kernel(const float* __restrict__ Dvec){
    extern __shared__ float smf[];
    float* CtT = smf;
    float* BsS = CtT + 64*68;
    float* XsH = BsS + 64*68;
    float* cAt = XsH + 64*68;
    float* dss = cAt + 64;
    float* qv  = dss + 64;
    int c = blockIdx.x, h = blockIdx.y, b = blockIdx.z;
    int bh = b*Hh + h;
    int tid = threadIdx.x;
    int ty = tid>>4, tx = tid&15;
    size_t rowt = (size_t)(b*Lseq + c*64);

#pragma unroll
    for (int cc=0; cc<8; cc++){
        int idx = cc*128 + tid;
        int r = idx>>4, n4 = (idx&15)*4;
        float4 v = *(const float4*)&g_xbc[(rowt + r)*XBCd + DI + DSm + n4];
        CtT[(n4+0)*68 + r] = v.x;
        CtT[(n4+1)*68 + r] = v.y;
        CtT[(n4+2)*68 + r] = v.z;
        CtT[(n4+3)*68 + r] = v.w;
        float4 bv = *(const float4*)&g_xbc[(rowt + r)*XBCd + DI + n4];
        BsS[(n4+0)*68 + r] = bv.x;
        BsS[(n4+1)*68 + r] = bv.y;
        BsS[(n4+2)*68 + r] = bv.z;
        BsS[(n4+3)*68 + r] = bv.w;
        float4 xv = *(const float4*)&g_xbc[(rowt + r)*XBCd + h*HDm + n4];
        *(float4*)&XsH[r*68 + n4] = xv;
    }
    if (tid < 64){
        float ca = g_cA[(size_t)bh*Lseq + c*64 + tid];
        cAt[tid] = ca;
        dss[tid] = g_dt[(size_t)bh*Lseq + c*64 + tid];
        qv[tid]  = (c > 0) ? expf(ca - g_E[bh*NCH + c - 1]) : 0.f;
    }
    __syncthreads();

    u64 cb2[8][2];
#pragma unroll
    for (int i=0;i<8;i++){ cb2[i][0]=0ULL; cb2[i][1]=0ULL; }
#pragma unroll 8
    for (int n=0;n<64;n++){
        float4 a0 = *(const float4*)&CtT[n*68 + ty*8];
        float4 a1 = *(const float4*)&CtT[n*68 + ty*8 + 4];
        ulonglong2 bp = *(const ulonglong2*)&BsS[n*68 + tx*4];
        u64 ap[8];
        ap[0]=pk2(a0.x); ap[1]=pk2(a0.y); ap[2]=pk2(a0.z); ap[3]=pk2(a0.w);
        ap[4]=pk2(a1.x); ap[5]=pk2(a1.y); ap[6]=pk2(a1.z); ap[7]=pk2(a1.w);
#pragma unroll
        for (int i=0;i<8;i++){
            fma2(cb2[i][0], ap[i], bp.x);
            fma2(cb2[i][1], ap[i], bp.y);
        }
    }
    __syncthreads();
    float d[8][4];
#pragma unroll
    for (int i=0;i<8;i++){
        int t = ty*8+i;
        float ca = cAt[t];
        float2 p0 = upk(cb2[i][0]);
        float2 p1 = upk(cb2[i][1]);
        float cbv[4] = {p0.x, p0.y, p1.x, p1.y};
#pragma unroll
        for (int j=0;j<4;j++){
            int s = tx*4+j;
            float v = 0.f;
            if (s <= t) v = expf(ca - cAt[s]) * cbv[j] * dss[s];
            d[i][j] = v;
        }
    }
#pragma unroll
    for (int j=0;j<4;j++){
        int s = tx*4+j;
        float4 v0 = make_float4(d[0][j],d[1][j],d[2][j],d[3][j]);
        float4 v1 = make_float4(d[4][j],d[5][j],d[6][j],d[7][j]);
        *(float4*)&BsS[s*68 + ty*8]   = v0;
        *(float4*)&BsS[s*68 + ty*8+4] = v1;
    }
    __syncthreads();
    u64 yacc2[8][2];
#pragma unroll
    for (int i=0;i<8;i++){ yacc2[i][0]=0ULL; yacc2[i][1]=0ULL; }
#pragma unroll 8
    for (int s=0;s<64;s++){
        float4 a0 = *(const float4*)&BsS[s*68 + ty*8];
        float4 a1 = *(const float4*)&BsS[s*68 + ty*8 + 4];
        ulonglong2 xp = *(const ulonglong2*)&XsH[s*68 + tx*4];
        u64 ap[8];
        ap[0]=pk2(a0.x); ap[1]=pk2(a0.y); ap[2]=pk2(a0.z); ap[3]=pk2(a0.w);
        ap[4]=pk2(a1.x); ap[5]=pk2(a1.y); ap[6]=pk2(a1.z); ap[7]=pk2(a1.w);
#pragma unroll
        for (int i=0;i<8;i++){
            fma2(yacc2[i][0], ap[i], xp.x);
            fma2(yacc2[i][1], ap[i], xp.y);
        }
    }
    __syncthreads();
    u64 zacc2[8][2];
#pragma unroll
    for (int i=0;i<8;i++){ zacc2[i][0]=0ULL; zacc2[i][1]=0ULL; }
    if (c > 0){
        const float* H = g_Hst + ((size_t)bh*NCH + c)*4096;
#pragma unroll
        for (int cc=0; cc<8; cc++){
            int idx = cc*128 + tid;
            int n = idx>>4, p4 = (idx&15)*4;
            float4 hv = *(const float4*)&H[n*64 + p4];
            *(float4*)&XsH[n*68 + p4] = hv;
        }
        __syncthreads();
#pragma unroll 8
        for (int n=0;n<64;n++){
            float4 a0 = *(const float4*)&CtT[n*68 + ty*8];
            float4 a1 = *(const float4*)&CtT[n*68 + ty*8 + 4];
            ulonglong2 hp = *(const ulonglong2*)&XsH[n*68 + tx*4];
            u64 ap[8];
            ap[0]=pk2(a0.x); ap[1]=pk2(a0.y); ap[2]=pk2(a0.z); ap[3]=pk2(a0.w);
            ap[4]=pk2(a1.x); ap[5]=pk2(a1.y); ap[6]=pk2(a1.z); ap[7]=pk2(a1.w);
#pragma unroll
            for (int i=0;i<8;i++){
                fma2(zacc2[i][0], ap[i], hp.x);
                fma2(zacc2[i][1], ap[i], hp.y);
            }
        }
    }
    float Dh = Dvec[h];
#pragma unroll
    for (int i=0;i<8;i++){
        int t = ty*8+i;
        float q = qv[t];
        float4 xv = *(const float4*)&g_xbc[(rowt+t)*XBCd + h*HDm + tx*4];
        float2 p0 = upk(yacc2[i][0]);
        float2 p1 = upk(yacc2[i][1]);
        float2 z0 = upk(zacc2[i][0]);
        float2 z1 = upk(zacc2[i][1]);
        float4 o;
        o.x = p0.x + q*z0.x + Dh*xv.x;
        o.y = p0.y + q*z0.y + Dh*xv.y;
        o.z = p1.x + q*z1.x + Dh*xv.z;
        o.w = p1.y + q*z1.y + Dh*xv.w;
        *(float4*)&g_y[(rowt+t)*DI + h*HDm + tx*4] = o;
    }
}

// ---------------- gated RMS norm: one warp per row (DI=512) ----------------
__global__ __launch_bounds__(256)
void gated_rms_warp(const float* __restrict__ nw){
    int wr = threadIdx.x >> 5, lane = threadIdx.x & 31;
    int row = blockIdx.x*8 + wr;
    float* Yr = g_y + (size_t)row*DI;
    const float* Zr = g_zx + (size_t)row*DIPd;
    float gg[16];
    float q = 0.f;
#pragma unroll
    for (int c=0;c<4;c++){
        int col = lane*4 + c*128;
        float4 yv = *(const float4*)(Yr + col);
        float4 zv = *(const float4*)(Zr + col);
        float g0 = yv.x * siluf(zv.x);
        float g1 = yv.y * siluf(zv.y);
        float g2 = yv.z * siluf(zv.z);
        float g3 = yv.w * siluf(zv.w);
        gg[c*4+0]=g0; gg[c*4+1]=g1; gg[c*4+2]=g2; gg[c*4+3]=g3;
        q += g0*g0 + g1*g1 + g2*g2 + g3*g3;
    }
#pragma unroll
    for (int off=16; off; off>>=1) q += __shfl_xor_sync(0xffffffffu, q, off);
    float scale = rsqrtf(q*(1.f/DI) + 1e-5f);
#pragma unroll
    for (int c=0;c<4;c++){
        int col = lane*4 + c*128;
        float4 wv = *(const float4*)(nw + col);
        float4 o;
        o.x = gg[c*4+0]*scale*wv.x;
        o.y = gg[c*4+1]*scale*wv.y;
        o.z = gg[c*4+2]*scale*wv.z;
        o.w = gg[c*4+3]*scale*wv.w;
        *(float4*)(Yr + col) = o;
    }
}

// ---------------- fused flash attention (non-causal, HD=64) ----------------
__global__ __launch_bounds__(128)
void flash_attn_kernel(){
    __shared__ float QT[64*68];
    __shared__ float KT[64*68];
    __shared__ float Vs[64*68];
    __shared__ float PT[64*68];
    int tt = blockIdx.x, h = blockIdx.y, b = blockIdx.z;
    int tid = threadIdx.x;
    int ty = tid>>4, tx = tid&15;

#pragma unroll
    for (int c=0;c<8;c++){
        int idx = c*128 + tid;
        int r = idx>>4, p4 = (idx&15)*4;
        float4 q = *(const float4*)&g_qkv[(size_t)(b*Lseq + tt*64 + r)*(3*Dm) + h*AHDd + p4];
        QT[(p4+0)*68 + r] = q.x*0.125f;
        QT[(p4+1)*68 + r] = q.y*0.125f;
        QT[(p4+2)*68 + r] = q.z*0.125f;
        QT[(p4+3)*68 + r] = q.w*0.125f;
    }

    float m[8], l[8];
    u64 oacc[8][2];
#pragma unroll
    for (int i=0;i<8;i++){ m[i] = -1e30f; l[i] = 0.f; oacc[i][0]=0ULL; oacc[i][1]=0ULL; }

    for (int st=0; st<16; st++){
        __syncthreads();
#pragma unroll
        for (int c=0;c<8;c++){
            int idx = c*128 + tid;
            int r = idx>>4, p4 = (idx&15)*4;
            float4 k = *(const float4*)&g_qkv[(size_t)(b*Lseq + st*64 + r)*(3*Dm) + Dm + h*AHDd + p4];
            KT[(p4+0)*68 + r] = k.x;
            KT[(p4+1)*68 + r] = k.y;
            KT[(p4+2)*68 + r] = k.z;
            KT[(p4+3)*68 + r] = k.w;
            float4 vv = *(const float4*)&g_qkv[(size_t)(b*Lseq + st*64 + r)*(3*Dm) + 2*Dm + h*AHDd + p4];
            *(float4*)&Vs[r*68 + p4] = vv;
        }
        __syncthreads();
        u64 sacc[8][2];
#pragma unroll
        for (int i=0;i<8;i++){ sacc[i][0]=0ULL; sacc[i][1]=0ULL; }
#pragma unroll 8
        for (int p=0;p<64;p++){
            float4 a0 = *(const float4*)&QT[p*68 + ty*8];
            float4 a1 = *(const float4*)&QT[p*68 + ty*8 + 4];
            ulonglong2 bp = *(const ulonglong2*)&KT[p*68 + tx*4];
            u64 ap[8];
            ap[0]=pk2(a0.x); ap[1]=pk2(a0.y); ap[2]=pk2(a0.z); ap[3]=pk2(a0.w);
            ap[4]=pk2(a1.x); ap[5]=pk2(a1.y); ap[6]=pk2(a1.z); ap[7]=pk2(a1.w);
#pragma unroll
            for (int i=0;i<8;i++){
                fma2(sacc[i][0], ap[i], bp.x);
                fma2(sacc[i][1], ap[i], bp.y);
            }
        }
        float pbuf[8][4];
#pragma unroll
        for (int i=0;i<8;i++){
            float2 s0 = upk(sacc[i][0]);
            float2 s1 = upk(sacc[i][1]);
            float sv[4] = {s0.x, s0.y, s1.x, s1.y};
            float mx = fmaxf(fmaxf(sv[0],sv[1]), fmaxf(sv[2],sv[3]));
#pragma unroll
            for (int off=8; off; off>>=1)
                mx = fmaxf(mx, __shfl_xor_sync(0xffffffffu, mx, off, 16));
            float mnew = fmaxf(m[i], mx);
            float scale = expf(m[i] - mnew);
            float psum = 0.f;
#pragma unroll
            for (int j=0;j<4;j++){ pbuf[i][j] = expf(sv[j] - mnew); psum += pbuf[i][j]; }
#pragma unroll
            for (int off=8; off; off>>=1)
                psum += __shfl_xor_sync(0xffffffffu, psum, off, 16);
            l[i] = l[i]*scale + psum;
            m[i] = mnew;
            float2 q0 = upk(oacc[i][0]);
            float2 q1 = upk(oacc[i][1]);
            oacc[i][0] = pk2ab(q0.x*scale, q0.y*scale);
            oacc[i][1] = pk2ab(q1.x*scale, q1.y*scale);
        }
#pragma unroll
        for (int j=0;j<4;j++){
            int s = tx*4+j;
            *(float4*)&PT[s*68 + ty*8]   = make_float4(pbuf[0][j],pbuf[1][j],pbuf[2][j],pbuf[3][j]);
            *(float4*)&PT[s*68 + ty*8+4] = make_float4(pbuf[4][j],pbuf[5][j],pbuf[6][j],pbuf[7][j]);
        }
        __syncthreads();
#pragma unroll 8
        for (int s=0;s<64;s++){
            float4 a0 = *(const float4*)&PT[s*68 + ty*8];
            float4 a1 = *(const float4*)&PT[s*68 + ty*8 + 4];
            ulonglong2 xp = *(const ulonglong2*)&Vs[s*68 + tx*4];
            u64 ap[8];
            ap[0]=pk2(a0.x); ap[1]=pk2(a0.y); ap[2]=pk2(a0.z); ap[3]=pk2(a0.w);
            ap[4]=pk2(a1.x); ap[5]=pk2(a1.y); ap[6]=pk2(a1.z); ap[7]=pk2(a1.w);
#pragma unroll
            for (int i=0;i<8;i++){
                fma2(oacc[i][0], ap[i], xp.x);
                fma2(oacc[i][1], ap[i], xp.y);
            }
        }
    }
#pragma unroll
    for (int i=0;i<8;i++){
        float inv = 1.f / l[i];
        float2 p0 = upk(oacc[i][0]);
        float2 p1 = upk(oacc[i][1]);
        float4 v = make_float4(p0.x*inv, p0.y*inv, p1.x*inv, p1.y*inv);
        *(float4*)&g_attnO[(size_t)(b*Lseq + tt*64 + ty*8+i)*Dm + h*AHDd + tx*4] = v;
    }
}

// ---------------- mean over L ----------------
__global__ __launch_bounds__(1024)
void mean_kernel(){
    __shared__ float part[4][256];
    int b = blockIdx.x;
    int t = threadIdx.x;
    int d = t & 255, lg = t >> 8;
    float s = 0.f;
    for (int l = lg; l < Lseq; l += 4) s += g_lnbuf[(size_t)(b*Lseq + l)*Dm + d];
    part[lg][d] = s;
    __syncthreads();
    if (t < 256) g_hm[b*Dm + t] = (part[0][t]+part[1][t]+part[2][t]+part[3][t])*(1.f/Lseq);
}

// ---------------- output heads ----------------
__global__ void head_kernel(const float* __restrict__ dw, const float* __restrict__ db,
                            const float* __restrict__ rw, const float* __restrict__ rb,
                            float* __restrict__ out){
    int t = threadIdx.x; if (t >= 24) return;
    int which = t/12; int b = (t%12)/3; int j = t%3;
    const float* W  = which ? rw : dw;
    const float* bs = which ? rb : db;
    float acc = bs[j];
    for (int d = 0; d < Dm; d++) acc += g_hm[b*Dm + d]*W[d*3 + j];
    out[which*12 + b*3 + j] = acc;
}

// ---------------- launch ----------------
extern "C" void kernel_launch(void* const* d_in, const int* in_sizes, int n_in,
                              void* d_out, int out_size){
    const float* x          = (const float*)d_in[0];
    const float* pos_emb    = (const float*)d_in[1];
    const float* in_w       = (const float*)d_in[2];
    const float* in_b       = (const float*)d_in[3];
    const float* ln1_w      = (const float*)d_in[4];
    const float* ln1_b      = (const float*)d_in[5];
    const float* ssm_in_w   = (const float*)d_in[6];
    const float* ssm_conv_w = (const float*)d_in[7];
    const float* ssm_conv_b = (const float*)d_in[8];
    const float* ssm_dt_bias= (const float*)d_in[9];
    const float* ssm_A_log  = (const float*)d_in[10];
    const float* ssm_D      = (const float*)d_in[11];
    const float* ssm_norm_w = (const float*)d_in[12];
    const float* ssm_out_w  = (const float*)d_in[13];
    const float* ln2_w      = (const float*)d_in[14];
    const float* ln2_b      = (const float*)d_in[15];
    const float* fc1_w      = (const float*)d_in[16];
    const float* fc1_b      = (const float*)d_in[17];
    const float* fc2_w      = (const float*)d_in[18];
    const float* fc2_b      = (const float*)d_in[19];
    const float* attn_ln_w  = (const float*)d_in[20];
    const float* attn_ln_b  = (const float*)d_in[21];
    const float* attn_qkv_w = (const float*)d_in[22];
    const float* attn_qkv_b = (const float*)d_in[23];
    const float* attn_out_w = (const float*)d_in[24];
    const float* attn_out_b = (const float*)d_in[25];
    const float* norm_w     = (const float*)d_in[26];
    const float* norm_b     = (const float*)d_in[27];
    const float* dir_w      = (const float*)d_in[28];
    const float* dir_b      = (const float*)d_in[29];
    const float* reg_w      = (const float*)d_in[30];
    const float* reg_b      = (const float*)d_in[31];
    float* out = (float*)d_out;

    cudaFuncSetAttribute(mamba_kernel, cudaFuncAttributeMaxDynamicSharedMemorySize, MSMEM);

    float *ph, *pln, *pzx, *py, *pqkv, *pattnO, *pff2;
    cudaGetSymbolAddress((void**)&ph,     g_h);
    cudaGetSymbolAddress((void**)&pln,    g_lnbuf);
    cudaGetSymbolAddress((void**)&pzx,    g_zx);
    cudaGetSymbolAddress((void**)&py,     g_y);
    cudaGetSymbolAddress((void**)&pqkv,   g_qkv);
    cudaGetSymbolAddress((void**)&pattnO, g_attnO);
    cudaGetSymbolAddress((void**)&pff2,   g_ff2);

    embed_kernel<<<ROWS, 256>>>(x, in_w, in_b, pos_emb);

    for (int i = 0; i < NLAY; i++){
        // ---- Mamba2 branch ----
        ln_warp<<<ROWS/8, 256>>>(ph, ln1_w + i*Dm, ln1_b + i*Dm, pln);
        gemm64n<<<dim3((DIPd+63)/64, ROWS/128), 256>>>(
            pln, ssm_in_w + (size_t)i*Dm*DIPd, nullptr, pzx, 256, DIPd, 0);
        conv_silu_kernel<<<dim3(XBCd/128, ROWS/8), 128>>>(
            ssm_conv_w + (size_t)i*Kc*XBCd, ssm_conv_b + (size_t)i*XBCd);
        dtcum_kernel<<<Bb*Hh, 1024>>>(ssm_dt_bias + i*Hh, ssm_A_log + i*Hh);
        mstate_kernel<<<dim3(NCH, Hh, Bb), 128>>>();
        mscan_kernel<<<Bb*Hh, 512>>>();
        mamba_kernel<<<dim3(NCH, Hh, Bb), 128, MSMEM>>>(ssm_D + i*Hh);
        gated_rms_warp<<<ROWS/8, 256>>>(ssm_norm_w + (size_t)i*DI);
        gemm64x64<<<dim3(Dm/64, ROWS/64), 128>>>(
            py, ssm_out_w + (size_t)i*DI*Dm, nullptr, ph, 512, Dm, 1);

        // ---- attention (odd layers) ----
        if (i & 1){
            int j = i >> 1;
            ln_warp<<<ROWS/8, 256>>>(ph, attn_ln_w + j*Dm, attn_ln_b + j*Dm, pln);
            gemm64n<<<dim3(3*Dm/64, ROWS/128), 256>>>(
                pln, attn_qkv_w + (size_t)j*Dm*3*Dm, attn_qkv_b + (size_t)j*3*Dm, pqkv, 256, 3*Dm, 0);
            flash_attn_kernel<<<dim3(16, AHn, Bb), 128>>>();
            gemm64x64<<<dim3(Dm/64, ROWS/64), 128>>>(
                pattnO, attn_out_w + (size_t)j*Dm*Dm, attn_out_b + (size_t)j*Dm, ph, 256, Dm, 1);
        }

        // ---- gMLP ----
        ln_warp<<<ROWS/8, 256>>>(ph, ln2_w + i*Dm, ln2_b + i*Dm, pln);
        gemm_fc1<<<dim3(8, ROWS/128), 256>>>(
            pln, fc1_w + (size_t)i*Dm*2*DFFd, fc1_b + (size_t)i*2*DFFd, pff2, 256);
        gemm64x64<<<dim3(Dm/64, ROWS/64), 128>>>(
            pff2, fc2_w + (size_t)i*DFFd*Dm, fc2_b + (size_t)i*Dm, ph, 512, Dm, 1);
    }

    // ---- final norm, mean, heads ----
    ln_warp<<<ROWS/8, 256>>>(ph, norm_w, norm_b, pln);
    mean_kernel<<<Bb, 1024>>>();
    head_kernel<<<1, 32>>>(dir_w, dir_b, reg_w, reg_b, out);
}